// round 17
// baseline (speedup 1.0000x reference)
#include <cuda_runtime.h>

// QSP expectation, single fused kernel, zero inter-block communication.
// Grid 128 x 1024 (one block per SM).
//
// SU(2) factorization: every step matrix M_k = W(th)*S(phi_k) is
// [[a_k, b_k], [-conj(b_k), conj(a_k)]] with a_k = c*e^{i phi}, b_k = i*s*e^{-i phi};
// products stay SU(2), so a partial product is 2 complex numbers (a, b).
// Per block:
//   1) setup: 54 accurate sincosf of phases (threads 0-53) + phi0 (t=60).
//   2) chain: 1024 threads = 4 segments (14/14/13/13 steps) x 256 grid
//      points theta_j = pi*j/256; each thread computes its segment's (a,b).
//   3) combine: threads 0-255 do 3 SU(2) products -> P00 -> g[j].
//   4) cf: monomial cubic coeffs per interval (threads 0-255, bar256).
//   5) eval: range-reduce + one LDS.128 + 3-fma Horner, 4 elems/thread.
// No DFT, no Clenshaw — the mid-section is gone.

#define NSTEP 54
#define TSIZE 256

__device__ __forceinline__ void bar256() {
    asm volatile("bar.sync 2, 256;" ::: "memory");
}

__global__ void __launch_bounds__(1024, 1)
qsp_fused(const float4* __restrict__ x4,
          const float*  __restrict__ phis,
          const float4* __restrict__ a4,
          const float*  __restrict__ bias,
          float4* __restrict__ out4,
          int nq)                       // nq = n/4
{
    __shared__ float pc[NSTEP], ps[NSTEP];
    __shared__ float s0cs[2];
    __shared__ __align__(16) float4 sQ[4 * TSIZE];   // per-segment (ax,ay,bx,by)
    __shared__ __align__(16) float  g[TSIZE];        // g on the grid
    __shared__ __align__(16) float4 cf[TSIZE];       // monomial cubic coeffs

    const int t = threadIdx.x;
    const int T = blockIdx.x * blockDim.x + t;
    const bool act = (T < nq);

    // ---- eval-path global loads issued FIRST ----
    float4 xv = make_float4(0.f, 0.f, 0.f, 0.f);
    float4 av = xv;
    if (act) { xv = x4[T]; av = a4[T]; }
    const float bb = bias[0];

    // ---- setup: phase sin/cos (accurate, one-time) ----
    if (t < NSTEP) {
        float sp, cp; sincosf(phis[t + 1], &sp, &cp);
        pc[t] = cp; ps[t] = sp;
    }
    if (t == 60) {
        float sp, cp; sincosf(phis[0], &sp, &cp);
        s0cs[0] = cp; s0cs[1] = sp;
    }
    __syncthreads();

    // ---- segment chain: seg = t>>8 (0..3), grid point j = t&255 ----
    {
        const int seg = t >> 8;
        const int j   = t & (TSIZE - 1);
        const int base = seg * 14 - (seg == 3 ? 1 : 0);   // 0,14,28,41
        const bool extra = (seg < 2);                      // 14 vs 13 steps

        // theta_j = pi * j / 256
        float s, c;
        sincospif((float)j * (1.0f / 256.0f), &s, &c);

        float ax = 1.f, ay = 0.f, bx = 0.f, by = 0.f;     // (a,b) = identity

        #pragma unroll
        for (int kk = 0; kk < 14; ++kk) {
            if (kk == 13 && !extra) break;
            const float ec = pc[base + kk], es = ps[base + kk];
            // M_k components: a_k=(c*ec, c*es), b_k=(s*es, s*ec)
            const float akx = c * ec, aky = c * es;
            const float bkx = s * es, bky = s * ec;
            // (a,b) <- (a*a_k - b*conj(b_k),  a*b_k + b*conj(a_k))
            const float nax = ax*akx - ay*aky - bx*bkx - by*bky;
            const float nay = ax*aky + ay*akx + bx*bky - by*bkx;
            const float nbx = ax*bkx - ay*bky + bx*akx + by*aky;
            const float nby = ax*bky + ay*bkx - bx*aky + by*akx;
            ax = nax; ay = nay; bx = nbx; by = nby;
        }

        sQ[t] = make_float4(ax, ay, bx, by);
    }
    __syncthreads();

    // ---- combine + g + cf: threads 0-255 ----
    if (t < TSIZE) {
        const float4 q0 = sQ[t];
        const float4 q1 = sQ[t + TSIZE];
        const float4 q2 = sQ[t + 2 * TSIZE];
        const float4 q3 = sQ[t + 3 * TSIZE];

        // R = Q0*Q1
        const float rax = (q0.x*q1.x - q0.y*q1.y) - (q0.z*q1.z + q0.w*q1.w);
        const float ray = (q0.x*q1.y + q0.y*q1.x) - (q0.w*q1.z - q0.z*q1.w);
        const float rbx = (q0.x*q1.z - q0.y*q1.w) + (q0.z*q1.x + q0.w*q1.y);
        const float rby = (q0.x*q1.w + q0.y*q1.z) + (q0.w*q1.x - q0.z*q1.y);
        // S = Q2*Q3
        const float sax = (q2.x*q3.x - q2.y*q3.y) - (q2.z*q3.z + q2.w*q3.w);
        const float say = (q2.x*q3.y + q2.y*q3.x) - (q2.w*q3.z - q2.z*q3.w);
        const float sbx = (q2.x*q3.z - q2.y*q3.w) + (q2.z*q3.x + q2.w*q3.y);
        const float sby = (q2.x*q3.w + q2.y*q3.z) + (q2.w*q3.x - q2.z*q3.y);
        // alpha(P) = aR*aS - bR*conj(bS)
        const float px = (rax*sax - ray*say) - (rbx*sbx + rby*sby);
        const float py = (rax*say + ray*sax) - (rby*sbx - rbx*sby);

        g[t] = s0cs[0] * px - s0cs[1] * py;   // Re(e^{i phi0} * P00)

        bar256();

        const float gm = g[(t + TSIZE - 1) & (TSIZE - 1)];
        const float g0 = g[t];
        const float gp = g[(t + 1) & (TSIZE - 1)];
        const float gq = g[(t + 2) & (TSIZE - 1)];
        const float c1 = gp - gm * (1.0f/3.0f) - g0 * 0.5f - gq * (1.0f/6.0f);
        const float c2 = 0.5f * (gm + gp) - g0;
        const float c3 = (3.0f * (g0 - gp) + gq - gm) * (1.0f/6.0f);
        cf[t] = make_float4(g0, c1, c2, c3);
    }
    __syncthreads();

    // ---- evaluation: range-reduce + LDS.128 + 3-fma Horner ----
    if (!act) return;

    const float SCALE = (float)TSIZE / 3.14159265358979323846f;
    float th[4] = {xv.x, xv.y, xv.z, xv.w};
    float res[4];
    #pragma unroll
    for (int e = 0; e < 4; ++e) {
        const float u  = th[e] * SCALE;
        const float fl = floorf(u);
        const float f  = u - fl;
        const int idx  = ((int)fl) & (TSIZE - 1);
        const float4 c = cf[idx];
        res[e] = fmaf(fmaf(fmaf(c.w, f, c.z), f, c.y), f, c.x);
    }

    out4[T] = make_float4(fmaf(av.x, res[0], bb), fmaf(av.y, res[1], bb),
                          fmaf(av.z, res[2], bb), fmaf(av.w, res[3], bb));
}

// ---------------------------------------------------------------------------
// Fallback for unexpected shapes (direct chain evaluation).
// ---------------------------------------------------------------------------
__global__ void __launch_bounds__(256)
qsp_generic(const float* __restrict__ x,
            const float* __restrict__ phis,
            const float* __restrict__ alphas,
            const float* __restrict__ bias,
            float* __restrict__ out,
            int n, int nsteps)
{
    __shared__ float pc[256], ps[256];
    __shared__ float s0c, s0s;
    int t = threadIdx.x;
    if (t < nsteps && t < 256) {
        float sp, cp; sincosf(phis[t + 1], &sp, &cp);
        pc[t] = cp; ps[t] = sp;
    }
    if (t == 0) {
        float sp, cp; sincosf(phis[0], &sp, &cp);
        s0c = cp; s0s = sp;
    }
    __syncthreads();

    const int i = blockIdx.x * blockDim.x + t;
    if (i >= n) return;

    float s, c; sincosf(x[i], &s, &c);
    float x0 = 1.0f, y0 = 0.0f, x1 = 0.0f, y1 = 0.0f;
    for (int k = 0; k < nsteps; ++k) {
        const float ec = (k < 256) ? pc[k] : cosf(phis[k + 1]);
        const float es = (k < 256) ? ps[k] : sinf(phis[k + 1]);
        const float ux = c * x0 - s * y1;
        const float uy = c * y0 + s * x1;
        const float vx = c * x1 - s * y0;
        const float vy = c * y1 + s * x0;
        x0 = ec * ux - es * uy;
        y0 = es * ux + ec * uy;
        x1 = ec * vx + es * vy;
        y1 = ec * vy - es * vx;
    }
    const float re = s0c * x0 - s0s * y0;
    out[i] = fmaf(alphas[i], re, bias[0]);
}

extern "C" void kernel_launch(void* const* d_in, const int* in_sizes, int n_in,
                              void* d_out, int out_size)
{
    const float* x      = (const float*)d_in[0];
    const float* phis   = (const float*)d_in[1];
    const float* alphas = (const float*)d_in[2];
    const float* bias   = (const float*)d_in[3];
    float* out = (float*)d_out;

    const int n      = in_sizes[0];
    const int nph    = in_sizes[1];
    const int nsteps = nph - 1;

    if (nsteps == NSTEP && (n & 3) == 0) {
        const int nq      = n >> 2;                   // float4 quads
        const int threads = 1024;
        const int blocks  = (nq + threads - 1) / threads;   // 128 for n=524288
        qsp_fused<<<blocks, threads>>>((const float4*)x, phis,
                                       (const float4*)alphas, bias,
                                       (float4*)out, nq);
    } else {
        const int threads = 256;
        const int blocks  = (n + threads - 1) / threads;
        qsp_generic<<<blocks, threads>>>(x, phis, alphas, bias, out, n, nsteps);
    }
}